// round 1
// baseline (speedup 1.0000x reference)
#include <cuda_runtime.h>
#include <cuda_bf16.h>
#include <math.h>

#define C 256
#define EPS 0.001f
#define SUMBLK 256
#define NPAIRS 10
#define NCHUNKS 128
#define BK 16

// ---------------- scratch (no allocation allowed) ----------------
__device__ float g_psum[SUMBLK * C];                 // per-block channel sums
__device__ float g_pG[(size_t)NPAIRS * NCHUNKS * 64 * 64]; // split-K SYRK partials
__device__ float g_G[C * C];                         // X^T X
__device__ float g_W[C * C];                         // L^{-1} (lower, upper zeroed)
__device__ float g_bias[C];                          // W @ m

__constant__ int c_pi[NPAIRS] = {0,0,0,0,1,1,1,2,2,3};
__constant__ int c_pj[NPAIRS] = {0,1,2,3,1,2,3,2,3,3};

// ---------------- 1) per-channel partial sums ----------------
__global__ __launch_bounds__(256) void colsum_kernel(const float* __restrict__ x, int rows) {
    int c = threadIdx.x;
    int rows_per = rows / gridDim.x;
    const float* p = x + (size_t)blockIdx.x * rows_per * C + c;
    float s = 0.f;
#pragma unroll 8
    for (int r = 0; r < rows_per; ++r) s += p[(size_t)r * C];
    g_psum[blockIdx.x * C + c] = s;
}

// ---------------- 2) SYRK partials: G = X^T X (64x64 tiles, split-K) ----------------
__global__ __launch_bounds__(256) void syrk_kernel(const float* __restrict__ x, int rows) {
    __shared__ float As[BK][64];
    __shared__ float Bs[BK][64];

    int p  = blockIdx.x;
    int ti = c_pi[p], tj = c_pj[p];
    int kper = rows / gridDim.y;
    int k0 = blockIdx.y * kper;

    int tid = threadIdx.x;
    int ty = tid >> 4, tx = tid & 15;       // 16x16 thread grid, 4x4 micro-tile
    int lr = tid >> 4;                      // loader row 0..15
    int lc = (tid & 15) << 2;               // loader col (float4)

    const float* baseI = x + (size_t)k0 * C + ti * 64;
    const float* baseJ = x + (size_t)k0 * C + tj * 64;

    float acc[4][4];
#pragma unroll
    for (int i = 0; i < 4; ++i)
#pragma unroll
        for (int j = 0; j < 4; ++j) acc[i][j] = 0.f;

    for (int kk = 0; kk < kper; kk += BK) {
        float4 av = *(const float4*)(baseI + (size_t)(kk + lr) * C + lc);
        float4 bv = *(const float4*)(baseJ + (size_t)(kk + lr) * C + lc);
        __syncthreads();
        *(float4*)&As[lr][lc] = av;
        *(float4*)&Bs[lr][lc] = bv;
        __syncthreads();
#pragma unroll
        for (int k = 0; k < BK; ++k) {
            float4 a = *(const float4*)&As[k][ty * 4];
            float4 b = *(const float4*)&Bs[k][tx * 4];
            acc[0][0] += a.x * b.x; acc[0][1] += a.x * b.y; acc[0][2] += a.x * b.z; acc[0][3] += a.x * b.w;
            acc[1][0] += a.y * b.x; acc[1][1] += a.y * b.y; acc[1][2] += a.y * b.z; acc[1][3] += a.y * b.w;
            acc[2][0] += a.z * b.x; acc[2][1] += a.z * b.y; acc[2][2] += a.z * b.z; acc[2][3] += a.z * b.w;
            acc[3][0] += a.w * b.x; acc[3][1] += a.w * b.y; acc[3][2] += a.w * b.z; acc[3][3] += a.w * b.w;
        }
    }

    float* dst = g_pG + ((size_t)p * gridDim.y + blockIdx.y) * 4096;
#pragma unroll
    for (int i = 0; i < 4; ++i) {
        float4 v = make_float4(acc[i][0], acc[i][1], acc[i][2], acc[i][3]);
        *(float4*)&dst[(ty * 4 + i) * 64 + tx * 4] = v;
    }
}

// ---------------- 3) deterministic reduction of SYRK partials ----------------
__global__ __launch_bounds__(256) void reduceG_kernel() {
    int p = blockIdx.x;
    int e = blockIdx.y * 256 + threadIdx.x;   // 0..4095
    const float* src = g_pG + (size_t)p * NCHUNKS * 4096 + e;
    float s = 0.f;
#pragma unroll 8
    for (int c = 0; c < NCHUNKS; ++c) s += src[(size_t)c * 4096];
    int ti = c_pi[p], tj = c_pj[p];
    int a = e >> 6, b = e & 63;
    g_G[(ti * 64 + a) * C + tj * 64 + b] = s;
    if (ti != tj) g_G[(tj * 64 + b) * C + ti * 64 + a] = s;
}

// ---------------- 4) mean finalize + Cholesky + L^{-1} + bias (single block) ----------------
// Packed lower-triangular L in dynamic shared: 256*257/2 floats = 131584 B.
extern "C" __global__ __launch_bounds__(256) void chol_kernel(int rows) {
    extern __shared__ float Lp[];
    __shared__ float m[C];
    int tid = threadIdx.x;

    // mean (fixed-order)
    {
        float s = 0.f;
#pragma unroll 8
        for (int b = 0; b < SUMBLK; ++b) s += g_psum[b * C + tid];
        m[tid] = s / (float)rows;
    }
    __syncthreads();

    // build packed A = (1-eps)/(n-1) * (G - n m m^T) + eps I
    const int TOT = C * (C + 1) / 2;   // 32896
    float scale = (1.f - EPS) / (float)(rows - 1);
    for (int idx = tid; idx < TOT; idx += 256) {
        int i = (int)((sqrtf(8.f * (float)idx + 1.f) - 1.f) * 0.5f);
        while ((i + 1) * (i + 2) / 2 <= idx) ++i;
        while (i * (i + 1) / 2 > idx) --i;
        int j = idx - i * (i + 1) / 2;
        float v = (g_G[i * C + j] - (float)rows * m[i] * m[j]) * scale;
        if (i == j) v += EPS;
        Lp[idx] = v;
    }
    __syncthreads();

    // in-place packed Cholesky
    for (int k = 0; k < C; ++k) {
        int pk = k * (k + 1) / 2 + k;
        if (tid == 0) Lp[pk] = sqrtf(Lp[pk]);
        __syncthreads();
        float inv = 1.f / Lp[pk];
        int i = k + 1 + tid;
        if (i < C) Lp[i * (i + 1) / 2 + k] *= inv;
        __syncthreads();
        if (i < C) {
            float* row = &Lp[i * (i + 1) / 2];
            float lik = row[k];
#pragma unroll 4
            for (int j = k + 1; j <= i; ++j)
                row[j] -= lik * Lp[j * (j + 1) / 2 + k];
        }
        __syncthreads();
    }

    // W = L^{-1}: thread tid owns column tid (forward substitution)
    {
        int j = tid;
        float wloc[C];
        for (int i = j; i < C; ++i) {
            const float* lrow = &Lp[i * (i + 1) / 2];
            float s = (i == j) ? 1.f : 0.f;
#pragma unroll 4
            for (int k = j; k < i; ++k) s -= lrow[k] * wloc[k];
            float w = s / lrow[i];
            wloc[i] = w;
            g_W[i * C + j] = w;
        }
        for (int i = 0; i < j; ++i) g_W[i * C + j] = 0.f;
    }
    __syncthreads();   // makes g_W visible block-wide

    // bias = W @ m
    {
        float s = 0.f;
#pragma unroll 4
        for (int j = 0; j <= tid; ++j) s += g_W[tid * C + j] * m[j];
        g_bias[tid] = s;
    }
}

// ---------------- 5) whitening: out = x @ W^T - bias ----------------
// Each block: 64 spatial rows x all 256 output channels. x read exactly once.
__global__ __launch_bounds__(256) void whiten_kernel(const float* __restrict__ x,
                                                     float* __restrict__ out) {
    __shared__ float As[BK][65];    // [k][m]
    __shared__ float Bs[BK][260];   // [k][i] = W[i][k]

    int m0 = blockIdx.x * 64;
    int tid = threadIdx.x;
    int ty = tid >> 4, tx = tid & 15;

    int alr = tid >> 2;             // 0..63 spatial row
    int alq = (tid & 3) << 2;       // k offset within BK (float4)
    int wn  = tid >> 2;             // base W row
    int wq  = tid & 3;              // float4 index within BK

    float acc[4][16];
#pragma unroll
    for (int i = 0; i < 4; ++i)
#pragma unroll
        for (int j = 0; j < 16; ++j) acc[i][j] = 0.f;

    for (int k0 = 0; k0 < C; k0 += BK) {
        float4 a = *(const float4*)(x + (size_t)(m0 + alr) * C + k0 + alq);
        float4 b0 = *(const float4*)(g_W + (size_t)(wn + 0)   * C + k0 + wq * 4);
        float4 b1 = *(const float4*)(g_W + (size_t)(wn + 64)  * C + k0 + wq * 4);
        float4 b2 = *(const float4*)(g_W + (size_t)(wn + 128) * C + k0 + wq * 4);
        float4 b3 = *(const float4*)(g_W + (size_t)(wn + 192) * C + k0 + wq * 4);
        __syncthreads();
        As[alq + 0][alr] = a.x; As[alq + 1][alr] = a.y;
        As[alq + 2][alr] = a.z; As[alq + 3][alr] = a.w;
        int kq = wq * 4;
        Bs[kq + 0][wn + 0] = b0.x;   Bs[kq + 1][wn + 0] = b0.y;   Bs[kq + 2][wn + 0] = b0.z;   Bs[kq + 3][wn + 0] = b0.w;
        Bs[kq + 0][wn + 64] = b1.x;  Bs[kq + 1][wn + 64] = b1.y;  Bs[kq + 2][wn + 64] = b1.z;  Bs[kq + 3][wn + 64] = b1.w;
        Bs[kq + 0][wn + 128] = b2.x; Bs[kq + 1][wn + 128] = b2.y; Bs[kq + 2][wn + 128] = b2.z; Bs[kq + 3][wn + 128] = b2.w;
        Bs[kq + 0][wn + 192] = b3.x; Bs[kq + 1][wn + 192] = b3.y; Bs[kq + 2][wn + 192] = b3.z; Bs[kq + 3][wn + 192] = b3.w;
        __syncthreads();

#pragma unroll
        for (int k = 0; k < BK; ++k) {
            float a0 = As[k][ty * 4 + 0];
            float a1 = As[k][ty * 4 + 1];
            float a2 = As[k][ty * 4 + 2];
            float a3 = As[k][ty * 4 + 3];
#pragma unroll
            for (int nt = 0; nt < 4; ++nt) {
                float4 b = *(const float4*)&Bs[k][nt * 64 + tx * 4];
                acc[0][nt * 4 + 0] += a0 * b.x; acc[0][nt * 4 + 1] += a0 * b.y; acc[0][nt * 4 + 2] += a0 * b.z; acc[0][nt * 4 + 3] += a0 * b.w;
                acc[1][nt * 4 + 0] += a1 * b.x; acc[1][nt * 4 + 1] += a1 * b.y; acc[1][nt * 4 + 2] += a1 * b.z; acc[1][nt * 4 + 3] += a1 * b.w;
                acc[2][nt * 4 + 0] += a2 * b.x; acc[2][nt * 4 + 1] += a2 * b.y; acc[2][nt * 4 + 2] += a2 * b.z; acc[2][nt * 4 + 3] += a2 * b.w;
                acc[3][nt * 4 + 0] += a3 * b.x; acc[3][nt * 4 + 1] += a3 * b.y; acc[3][nt * 4 + 2] += a3 * b.z; acc[3][nt * 4 + 3] += a3 * b.w;
            }
        }
    }

    // epilogue: subtract bias, store
#pragma unroll
    for (int nt = 0; nt < 4; ++nt) {
        float4 bj = *(const float4*)&g_bias[nt * 64 + tx * 4];
#pragma unroll
        for (int i = 0; i < 4; ++i) {
            float4 v = make_float4(acc[i][nt * 4 + 0] - bj.x,
                                   acc[i][nt * 4 + 1] - bj.y,
                                   acc[i][nt * 4 + 2] - bj.z,
                                   acc[i][nt * 4 + 3] - bj.w);
            *(float4*)&out[(size_t)(m0 + ty * 4 + i) * C + nt * 64 + tx * 4] = v;
        }
    }
}

// ---------------- launch ----------------
extern "C" void kernel_launch(void* const* d_in, const int* in_sizes, int n_in,
                              void* d_out, int out_size) {
    const float* x = (const float*)d_in[0];
    float* out = (float*)d_out;
    int rows = in_sizes[0] / C;          // 131072 for (32,64,64,256)

    colsum_kernel<<<SUMBLK, 256>>>(x, rows);
    syrk_kernel<<<dim3(NPAIRS, NCHUNKS), 256>>>(x, rows);
    reduceG_kernel<<<dim3(NPAIRS, 16), 256>>>();

    static const int chol_smem = (C * (C + 1) / 2) * (int)sizeof(float);  // 131584
    cudaFuncSetAttribute(chol_kernel, cudaFuncAttributeMaxDynamicSharedMemorySize, chol_smem);
    chol_kernel<<<1, 256, chol_smem>>>(rows);

    whiten_kernel<<<dim3(rows / 64, 1), 256>>>(x, out);
}